// round 14
// baseline (speedup 1.0000x reference)
#include <cuda_runtime.h>
#include <cuda_fp16.h>
#include <cstdint>

#define BATCH 8
#define SEQ   2048
#define DIM   512
#define TOK   (BATCH*SEQ)          // 16384

typedef __half fp16;

// ---------------------------------------------------------------------------
// Scratch (__device__ globals: allocation-guard safe)
// ---------------------------------------------------------------------------
__device__ fp16  g_Xf[(size_t)TOK * DIM];
__device__ fp16  g_WT[3][DIM * DIM];                       // W^T fp16
__device__ fp16  g_QK[2][(size_t)TOK * DIM];               // Q=0, K=1
__device__ fp16  g_Vt[(size_t)DIM * TOK];                  // V^T [512,16384]
__device__ float g_P [(size_t)BATCH * SEQ * SEQ];
__device__ fp16  g_Pf[(size_t)BATCH * SEQ * SEQ];

// ---------------------------------------------------------------------------
// Baseline-PTX helpers (sm_80+: valid for compute_103 target)
// ---------------------------------------------------------------------------
__device__ __forceinline__ uint32_t s2u(const void* p) {
    uint32_t a;
    asm("{ .reg .u64 t; cvta.to.shared.u64 t, %1; cvt.u32.u64 %0, t; }" : "=r"(a) : "l"(p));
    return a;
}
__device__ __forceinline__ void cp16(uint32_t saddr, const fp16* g) {
    asm volatile("cp.async.cg.shared.global [%0], [%1], 16;"
                 :: "r"(saddr), "l"(__cvta_generic_to_global(g)) : "memory");
}
__device__ __forceinline__ void cp_commit() {
    asm volatile("cp.async.commit_group;" ::: "memory");
}
template <int N>
__device__ __forceinline__ void cp_wait() {
    asm volatile("cp.async.wait_group %0;" :: "n"(N) : "memory");
}
__device__ __forceinline__ void ldsm4(uint32_t* d, uint32_t a) {
    asm volatile("ldmatrix.sync.aligned.m8n8.x4.shared.b16 {%0,%1,%2,%3}, [%4];"
                 : "=r"(d[0]), "=r"(d[1]), "=r"(d[2]), "=r"(d[3]) : "r"(a));
}
__device__ __forceinline__ void mma16816(float* c, const uint32_t* a, const uint32_t* b) {
    asm volatile("mma.sync.aligned.m16n8k16.row.col.f32.f16.f16.f32 "
                 "{%0,%1,%2,%3}, {%4,%5,%6,%7}, {%8,%9}, {%0,%1,%2,%3};"
                 : "+f"(c[0]), "+f"(c[1]), "+f"(c[2]), "+f"(c[3])
                 : "r"(a[0]), "r"(a[1]), "r"(a[2]), "r"(a[3]), "r"(b[0]), "r"(b[1]));
}

// ---------------------------------------------------------------------------
// Single-pass fp16 GEMM: C[M,N] = A·B^T  (both operands K-major fp16)
// CTA 128x128, BK=32, 256 threads. R13: warp tile 64x32 (8 warps as 2x4)
// -> 6 LDSM per 16 MMAs (was 6 per 8): halves L1/LDSM traffic per MMA.
// 4-stage cp.async pipeline, 2 CTAs/SM. EPI=0: fp32 C. EPI=1: fp16 C.
// grid = (N/128, M/128, batch)
// ---------------------------------------------------------------------------
#define STAGE_BYTES 16384          // 2 tiles x 8KB (A, B), 128 rows x 64B
#define NSTAGE      4
#define SMEM_BYTES  (NSTAGE * STAGE_BYTES)

template <int EPI>
__global__ __launch_bounds__(256, 2)
void gemm_mma(const fp16* __restrict__ A, int lda, size_t sA,
              const fp16* __restrict__ B, int ldb, size_t sB,
              float* __restrict__ C, fp16* __restrict__ Cf,
              int ldc, size_t sC, int Kd)
{
    extern __shared__ __align__(1024) char smem[];
    const uint32_t sbase = s2u(smem);

    const int tid  = threadIdx.x;
    const int lane = tid & 31;
    const int wid  = tid >> 5;
    const int wm   = wid >> 2;        // 0..1 -> m offset wm*64
    const int wn   = wid & 3;         // 0..3 -> n offset wn*32

    A += (size_t)blockIdx.z * sA;
    B += (size_t)blockIdx.z * sB;
    if (C)  C  += (size_t)blockIdx.z * sC;
    if (Cf) Cf += (size_t)blockIdx.z * sC;
    const size_t bm = (size_t)blockIdx.y * 128;
    const size_t bn = (size_t)blockIdx.x * 128;

    const int nch = Kd >> 5;          // chunks of 32

    // gmem->smem: per tile 512 chunks of 16B; thread does rows cr0, cr0+64.
    // Swizzle: xch = ch ^ ((row>>1)&3).
    const int cr0 = tid >> 2;          // 0..63
    const int cch = tid & 3;
    const uint32_t s0 = (uint32_t)cr0 * 64 + (uint32_t)((cch ^ ((cr0 >> 1) & 3)) << 4);

    auto load_stage = [&](int stage, int c) {
        const uint32_t so = sbase + (uint32_t)stage * STAGE_BYTES;
        const size_t ka = (size_t)(c << 5) + cch * 8;
        const fp16* a_p = A + (bm + cr0) * (size_t)lda + ka;
        const fp16* b_p = B + (bn + cr0) * (size_t)ldb + ka;
        const size_t r64a = (size_t)64 * lda, r64b = (size_t)64 * ldb;
        cp16(so +         s0,         a_p);
        cp16(so +         s0 + 4096u, a_p + r64a);
        cp16(so + 8192u + s0,         b_p);
        cp16(so + 8192u + s0 + 4096u, b_p + r64b);
        cp_commit();
    };

    // ldmatrix per-lane pieces
    const int lg = lane >> 3, lr = lane & 7;
    const int a_row_off = (lg & 1) * 8 + lr;   // A-op (m-major)
    const int a_ch_off  = lg >> 1;
    const int b_row_off = (lg >> 1) * 8 + lr;  // B-op (n-major)
    const int b_ch_off  = lg & 1;

    uint32_t af[4][4], bf[2][4];

    auto frag_load = [&](uint32_t sb, int ks) {
        #pragma unroll
        for (int mt = 0; mt < 4; mt++) {
            const int row = wm * 64 + mt * 16 + a_row_off;
            const int ch  = 2 * ks + a_ch_off;
            const uint32_t off = (uint32_t)row * 64 + (uint32_t)(((ch ^ ((row >> 1) & 3)) & 3) << 4);
            ldsm4(af[mt], sb + off);
        }
        #pragma unroll
        for (int p = 0; p < 2; p++) {
            const int row = wn * 32 + p * 16 + b_row_off;
            const int ch  = 2 * ks + b_ch_off;
            const uint32_t off = (uint32_t)row * 64 + (uint32_t)(((ch ^ ((row >> 1) & 3)) & 3) << 4);
            ldsm4(bf[p], sb + 8192u + off);
        }
    };

    float acc[4][4][4];
    #pragma unroll
    for (int mt = 0; mt < 4; mt++)
        #pragma unroll
        for (int nt = 0; nt < 4; nt++)
            #pragma unroll
            for (int q = 0; q < 4; q++) acc[mt][nt][q] = 0.0f;

    auto compute = [&]() {
        #pragma unroll
        for (int mt = 0; mt < 4; mt++)
            #pragma unroll
            for (int p = 0; p < 2; p++) {
                mma16816(acc[mt][2 * p],     af[mt], &bf[p][0]);
                mma16816(acc[mt][2 * p + 1], af[mt], &bf[p][2]);
            }
    };

    // 4-stage pipeline prologue: stages 0,1,2 in flight
    load_stage(0, 0);
    load_stage(1, 1);
    if (nch > 2) load_stage(2, 2);

    int slot = 0;
    for (int c = 0; c < nch; c++) {
        if (c + 2 < nch)      cp_wait<2>();
        else if (c + 1 < nch) cp_wait<1>();
        else                  cp_wait<0>();
        __syncthreads();

        const uint32_t sb = sbase + (uint32_t)slot * STAGE_BYTES;
        frag_load(sb, 0);
        compute();
        frag_load(sb, 1);
        compute();

        if (c + 3 < nch) {
            int nslot = slot + 3; if (nslot >= NSTAGE) nslot -= NSTAGE;
            load_stage(nslot, c + 3);
        }
        if (++slot == NSTAGE) slot = 0;
    }

    // Epilogue: m16n8k16 acc: c0,c1 -> (r, c),(r, c+1); c2,c3 -> (r+8, ..)
    const int er = lane >> 2, ec = (lane & 3) * 2;
    #pragma unroll
    for (int mt = 0; mt < 4; mt++) {
        const size_t row0 = bm + wm * 64 + mt * 16 + er;
        #pragma unroll
        for (int nt = 0; nt < 4; nt++) {
            const size_t col = bn + wn * 32 + nt * 8 + ec;
            if (EPI == 0) {
                float2 v0 = make_float2(acc[mt][nt][0], acc[mt][nt][1]);
                float2 v1 = make_float2(acc[mt][nt][2], acc[mt][nt][3]);
                *(float2*)&C[row0 * ldc + col]       = v0;
                *(float2*)&C[(row0 + 8) * ldc + col] = v1;
            } else {
                *(__half2*)&Cf[row0 * ldc + col] =
                    __halves2half2(__float2half_rn(acc[mt][nt][0]), __float2half_rn(acc[mt][nt][1]));
                *(__half2*)&Cf[(row0 + 8) * ldc + col] =
                    __halves2half2(__float2half_rn(acc[mt][nt][2]), __float2half_rn(acc[mt][nt][3]));
            }
        }
    }
}

// ---------------------------------------------------------------------------
// Merged prep kernel: one launch does
//   blocks [0, NCONV)          : x fp32 -> Xf fp16 (float4 per thread)
//   blocks [NCONV, NCONV+768)  : W{q,k,v} -> W^T fp16 (32x32 transpose)
// ---------------------------------------------------------------------------
#define NCONV ((TOK * DIM) / 1024)     // 8192 conversion blocks

__global__ __launch_bounds__(256)
void prep_all(const float4* __restrict__ x4, uint2* __restrict__ of,
              const float* __restrict__ Wq, const float* __restrict__ Wk,
              const float* __restrict__ Wv, fp16* __restrict__ WT)
{
    const int b = blockIdx.x;
    if (b < NCONV) {
        const size_t i = (size_t)b * 256 + threadIdx.x;
        float4 v = x4[i];
        fp16 h[4] = {__float2half_rn(v.x), __float2half_rn(v.y),
                     __float2half_rn(v.z), __float2half_rn(v.w)};
        of[i] = *(uint2*)h;
        return;
    }
    // wtrans part
    __shared__ float t[32][33];
    const int widx = b - NCONV;         // 0..767
    const int w    = widx >> 8;         // 0,1,2 -> Wq,Wk,Wv
    const int r    = widx & 255;
    const int bx = (r & 15) * 32, by = (r >> 4) * 32;
    const float* W = (w == 0) ? Wq : (w == 1) ? Wk : Wv;
    fp16* T = WT + (size_t)w * DIM * DIM;
    const int tx = threadIdx.x & 31, ty = threadIdx.x >> 5;
    #pragma unroll
    for (int i = ty; i < 32; i += 8)
        t[i][tx] = W[(size_t)(by + i) * DIM + bx + tx];
    __syncthreads();
    #pragma unroll
    for (int i = ty; i < 32; i += 8)
        T[(size_t)(bx + i) * DIM + by + tx] = __float2half_rn(t[tx][i]);   // W^T
}

// ---------------------------------------------------------------------------
// Row softmax of P (fp32) -> fp16. One block per row (2048 cols).
// ---------------------------------------------------------------------------
__global__ __launch_bounds__(256)
void softmax_half(const float* __restrict__ P, fp16* __restrict__ Pf)
{
    const float* p = P + (size_t)blockIdx.x * SEQ;
    const int tid = threadIdx.x;
    __shared__ float red[8];

    float4 a = *(const float4*)&p[tid * 4];
    float4 b = *(const float4*)&p[1024 + tid * 4];
    float v[8] = {a.x, a.y, a.z, a.w, b.x, b.y, b.z, b.w};

    float m = v[0];
    #pragma unroll
    for (int i = 1; i < 8; i++) m = fmaxf(m, v[i]);
    #pragma unroll
    for (int o = 16; o > 0; o >>= 1) m = fmaxf(m, __shfl_xor_sync(~0u, m, o));
    if ((tid & 31) == 0) red[tid >> 5] = m;
    __syncthreads();
    m = red[0];
    #pragma unroll
    for (int i = 1; i < 8; i++) m = fmaxf(m, red[i]);
    __syncthreads();

    const float sc = 0.044194173824159216f;   // 1/sqrt(512)
    float s = 0.0f;
    #pragma unroll
    for (int i = 0; i < 8; i++) { v[i] = __expf((v[i] - m) * sc); s += v[i]; }
    #pragma unroll
    for (int o = 16; o > 0; o >>= 1) s += __shfl_xor_sync(~0u, s, o);
    if ((tid & 31) == 0) red[tid >> 5] = s;
    __syncthreads();
    s = 0.0f;
    #pragma unroll
    for (int i = 0; i < 8; i++) s += red[i];
    const float rinv = 1.0f / s;

    fp16 h[8];
    #pragma unroll
    for (int i = 0; i < 8; i++) h[i] = __float2half_rn(v[i] * rinv);
    const size_t base = (size_t)blockIdx.x * SEQ;
    *(uint2*)&Pf[base + tid * 4]        = *(uint2*)&h[0];
    *(uint2*)&Pf[base + 1024 + tid * 4] = *(uint2*)&h[4];
}

// ---------------------------------------------------------------------------
extern "C" void kernel_launch(void* const* d_in, const int* in_sizes, int n_in,
                              void* d_out, int out_size)
{
    const float* x  = (const float*)d_in[0];
    const float* Wq = (const float*)d_in[1];
    const float* Wk = (const float*)d_in[2];
    const float* Wv = (const float*)d_in[3];
    float* out = (float*)d_out;

    fp16 *Xf, *WT, *QK, *Vt, *Pf;
    float* P;
    cudaGetSymbolAddress((void**)&Xf, g_Xf);
    cudaGetSymbolAddress((void**)&WT, g_WT);
    cudaGetSymbolAddress((void**)&QK, g_QK);
    cudaGetSymbolAddress((void**)&Vt, g_Vt);
    cudaGetSymbolAddress((void**)&P, g_P);
    cudaGetSymbolAddress((void**)&Pf, g_Pf);

    const size_t QKs = (size_t)TOK * DIM;

    cudaFuncSetAttribute(gemm_mma<0>, cudaFuncAttributeMaxDynamicSharedMemorySize, SMEM_BYTES);
    cudaFuncSetAttribute(gemm_mma<1>, cudaFuncAttributeMaxDynamicSharedMemorySize, SMEM_BYTES);

    // launch 1: all conversions (x -> fp16, W -> W^T fp16)
    prep_all<<<NCONV + 768, 256>>>((const float4*)x, (uint2*)Xf, Wq, Wk, Wv, WT);

    // launch 2: Q,K projections (z=0 Wq, z=1 Wk). C fp16.
    gemm_mma<1><<<dim3(4, 128, 2), 256, SMEM_BYTES>>>(
        Xf, DIM, 0, WT, DIM, (size_t)DIM * DIM,
        nullptr, QK, DIM, QKs, DIM);
    // launch 3: V^T = Wv^T @ X^T. C fp16.
    gemm_mma<1><<<dim3(128, 4, 1), 256, SMEM_BYTES>>>(
        WT + 2 * DIM * DIM, DIM, 0, Xf, DIM, 0,
        nullptr, Vt, TOK, 0, DIM);

    // launch 4: scores P[b] = Q[b] @ K[b]^T. fp32 out.
    gemm_mma<0><<<dim3(16, 16, BATCH), 256, SMEM_BYTES>>>(
        QK, DIM, (size_t)SEQ * DIM, QK + QKs, DIM, (size_t)SEQ * DIM,
        P, nullptr, SEQ, (size_t)SEQ * SEQ, DIM);

    // launch 5: softmax rows -> fp16 probs
    softmax_half<<<BATCH * SEQ, 256>>>(P, Pf);

    // launch 6: out[b] = P[b] @ V[b] via B = V^T (ldb = TOK). fp32 out.
    gemm_mma<0><<<dim3(4, 16, BATCH), 256, SMEM_BYTES>>>(
        Pf, SEQ, (size_t)SEQ * SEQ, Vt, TOK, (size_t)SEQ,
        out, nullptr, DIM, (size_t)SEQ * DIM, SEQ);
}

// round 15
// speedup vs baseline: 1.0452x; 1.0452x over previous
#include <cuda_runtime.h>
#include <cuda_fp16.h>
#include <cstdint>

#define BATCH 8
#define SEQ   2048
#define DIM   512
#define TOK   (BATCH*SEQ)          // 16384

typedef __half fp16;

// ---------------------------------------------------------------------------
// Scratch (__device__ globals: allocation-guard safe)
// ---------------------------------------------------------------------------
__device__ fp16  g_Xf[(size_t)TOK * DIM];
__device__ fp16  g_WT[3][DIM * DIM];                       // W^T fp16
__device__ fp16  g_QK[2][(size_t)TOK * DIM];               // Q=0, K=1
__device__ fp16  g_Vt[(size_t)DIM * TOK];                  // V^T [512,16384]
__device__ float g_P [(size_t)BATCH * SEQ * SEQ];
__device__ fp16  g_Pf[(size_t)BATCH * SEQ * SEQ];

// ---------------------------------------------------------------------------
// Baseline-PTX helpers (sm_80+: valid for compute_103 target)
// ---------------------------------------------------------------------------
__device__ __forceinline__ uint32_t s2u(const void* p) {
    uint32_t a;
    asm("{ .reg .u64 t; cvta.to.shared.u64 t, %1; cvt.u32.u64 %0, t; }" : "=r"(a) : "l"(p));
    return a;
}
__device__ __forceinline__ void cp16(uint32_t saddr, const fp16* g) {
    asm volatile("cp.async.cg.shared.global [%0], [%1], 16;"
                 :: "r"(saddr), "l"(__cvta_generic_to_global(g)) : "memory");
}
__device__ __forceinline__ void cp_commit() {
    asm volatile("cp.async.commit_group;" ::: "memory");
}
template <int N>
__device__ __forceinline__ void cp_wait() {
    asm volatile("cp.async.wait_group %0;" :: "n"(N) : "memory");
}
__device__ __forceinline__ void ldsm4(uint32_t* d, uint32_t a) {
    asm volatile("ldmatrix.sync.aligned.m8n8.x4.shared.b16 {%0,%1,%2,%3}, [%4];"
                 : "=r"(d[0]), "=r"(d[1]), "=r"(d[2]), "=r"(d[3]) : "r"(a));
}
__device__ __forceinline__ void mma16816(float* c, const uint32_t* a, const uint32_t* b) {
    asm volatile("mma.sync.aligned.m16n8k16.row.col.f32.f16.f16.f32 "
                 "{%0,%1,%2,%3}, {%4,%5,%6,%7}, {%8,%9}, {%0,%1,%2,%3};"
                 : "+f"(c[0]), "+f"(c[1]), "+f"(c[2]), "+f"(c[3])
                 : "r"(a[0]), "r"(a[1]), "r"(a[2]), "r"(a[3]), "r"(b[0]), "r"(b[1]));
}

// ---------------------------------------------------------------------------
// Single-pass fp16 GEMM: C[M,N] = A·B^T  (both operands K-major fp16)
// CTA 128x128, 256 threads, warp tile 32x64 (R12 — proven best geometry).
// R15: TWO BK=32 chunks per sync iteration (ring of 6 stages, one commit per
// 2-chunk group, cp_wait<1>): 64 MMAs/warp per barrier, syncs halved.
// 2 CTAs/SM. EPI=0: fp32 C. EPI=1: fp16 C.  grid = (N/128, M/128, batch)
// Requires nch even (K multiple of 64 — holds: 512, 2048).
// ---------------------------------------------------------------------------
#define STAGE_BYTES 16384          // 2 tiles x 8KB (A, B), 128 rows x 64B
#define NSTAGE      6
#define SMEM_BYTES  (NSTAGE * STAGE_BYTES)   // 96KB/CTA, 192KB for 2 CTAs

template <int EPI>
__global__ __launch_bounds__(256, 2)
void gemm_mma(const fp16* __restrict__ A, int lda, size_t sA,
              const fp16* __restrict__ B, int ldb, size_t sB,
              float* __restrict__ C, fp16* __restrict__ Cf,
              int ldc, size_t sC, int Kd)
{
    extern __shared__ __align__(1024) char smem[];
    const uint32_t sbase = s2u(smem);

    const int tid  = threadIdx.x;
    const int lane = tid & 31;
    const int wid  = tid >> 5;
    const int wm   = wid >> 1;        // 0..3 -> m offset wm*32
    const int wn   = wid & 1;         // 0..1 -> n offset wn*64

    A += (size_t)blockIdx.z * sA;
    B += (size_t)blockIdx.z * sB;
    if (C)  C  += (size_t)blockIdx.z * sC;
    if (Cf) Cf += (size_t)blockIdx.z * sC;
    const size_t bm = (size_t)blockIdx.y * 128;
    const size_t bn = (size_t)blockIdx.x * 128;

    const int nch = Kd >> 5;          // chunks of 32 (even)

    // gmem->smem: per tile 512 chunks of 16B; thread does rows cr0, cr0+64.
    // Swizzle: xch = ch ^ ((row>>1)&3).
    const int cr0 = tid >> 2;          // 0..63
    const int cch = tid & 3;
    const uint32_t s0 = (uint32_t)cr0 * 64 + (uint32_t)((cch ^ ((cr0 >> 1) & 3)) << 4);

    // load chunks c and c+1 (c even) into slots c%6, c%6+1; ONE commit group
    auto load_group = [&](int c) {
        const uint32_t so = sbase + (uint32_t)(c % NSTAGE) * STAGE_BYTES;
        const size_t r64a = (size_t)64 * lda, r64b = (size_t)64 * ldb;
        #pragma unroll
        for (int q = 0; q < 2; q++) {
            const uint32_t sq = so + (uint32_t)q * STAGE_BYTES;
            const size_t ka = (size_t)((c + q) << 5) + cch * 8;
            const fp16* a_p = A + (bm + cr0) * (size_t)lda + ka;
            const fp16* b_p = B + (bn + cr0) * (size_t)ldb + ka;
            cp16(sq +         s0,         a_p);
            cp16(sq +         s0 + 4096u, a_p + r64a);
            cp16(sq + 8192u + s0,         b_p);
            cp16(sq + 8192u + s0 + 4096u, b_p + r64b);
        }
        cp_commit();
    };

    // ldmatrix per-lane pieces
    const int lg = lane >> 3, lr = lane & 7;
    const int a_row_off = (lg & 1) * 8 + lr;   // A-op (m-major)
    const int a_ch_off  = lg >> 1;
    const int b_row_off = (lg >> 1) * 8 + lr;  // B-op (n-major)
    const int b_ch_off  = lg & 1;

    uint32_t af[2][4], bf[4][4];

    auto frag_load = [&](uint32_t sb, int ks) {
        #pragma unroll
        for (int mt = 0; mt < 2; mt++) {
            const int row = wm * 32 + mt * 16 + a_row_off;
            const int ch  = 2 * ks + a_ch_off;
            const uint32_t off = (uint32_t)row * 64 + (uint32_t)(((ch ^ ((row >> 1) & 3)) & 3) << 4);
            ldsm4(af[mt], sb + off);
        }
        #pragma unroll
        for (int p = 0; p < 4; p++) {
            const int row = wn * 64 + p * 16 + b_row_off;
            const int ch  = 2 * ks + b_ch_off;
            const uint32_t off = (uint32_t)row * 64 + (uint32_t)(((ch ^ ((row >> 1) & 3)) & 3) << 4);
            ldsm4(bf[p], sb + 8192u + off);
        }
    };

    float acc[2][8][4];
    #pragma unroll
    for (int mt = 0; mt < 2; mt++)
        #pragma unroll
        for (int nt = 0; nt < 8; nt++)
            #pragma unroll
            for (int q = 0; q < 4; q++) acc[mt][nt][q] = 0.0f;

    auto compute = [&]() {
        #pragma unroll
        for (int mt = 0; mt < 2; mt++)
            #pragma unroll
            for (int p = 0; p < 4; p++) {
                mma16816(acc[mt][2 * p],     af[mt], &bf[p][0]);
                mma16816(acc[mt][2 * p + 1], af[mt], &bf[p][2]);
            }
    };

    // prologue: groups for chunks 0-1 and 2-3 in flight
    load_group(0);
    if (nch > 2) load_group(2);

    for (int c = 0; c < nch; c += 2) {
        if (c + 2 < nch) cp_wait<1>(); else cp_wait<0>();
        __syncthreads();

        const uint32_t sbA = sbase + (uint32_t)(c % NSTAGE) * STAGE_BYTES;
        const uint32_t sbB = sbA + STAGE_BYTES;
        frag_load(sbA, 0); compute();
        frag_load(sbA, 1); compute();
        frag_load(sbB, 0); compute();
        frag_load(sbB, 1); compute();

        // issue next group AFTER compute (R6/R8 lesson). Target slots were
        // vacated by group (c-2) at the previous iteration's sync boundary.
        if (c + 4 < nch) load_group(c + 4);
    }

    // Epilogue: m16n8k16 acc: c0,c1 -> (r, c),(r, c+1); c2,c3 -> (r+8, ..)
    const int er = lane >> 2, ec = (lane & 3) * 2;
    #pragma unroll
    for (int mt = 0; mt < 2; mt++) {
        const size_t row0 = bm + wm * 32 + mt * 16 + er;
        #pragma unroll
        for (int nt = 0; nt < 8; nt++) {
            const size_t col = bn + wn * 64 + nt * 8 + ec;
            if (EPI == 0) {
                float2 v0 = make_float2(acc[mt][nt][0], acc[mt][nt][1]);
                float2 v1 = make_float2(acc[mt][nt][2], acc[mt][nt][3]);
                *(float2*)&C[row0 * ldc + col]       = v0;
                *(float2*)&C[(row0 + 8) * ldc + col] = v1;
            } else {
                *(__half2*)&Cf[row0 * ldc + col] =
                    __halves2half2(__float2half_rn(acc[mt][nt][0]), __float2half_rn(acc[mt][nt][1]));
                *(__half2*)&Cf[(row0 + 8) * ldc + col] =
                    __halves2half2(__float2half_rn(acc[mt][nt][2]), __float2half_rn(acc[mt][nt][3]));
            }
        }
    }
}

// ---------------------------------------------------------------------------
// Merged prep kernel: one launch does
//   blocks [0, NCONV)          : x fp32 -> Xf fp16 (float4 per thread)
//   blocks [NCONV, NCONV+768)  : W{q,k,v} -> W^T fp16 (32x32 transpose)
// ---------------------------------------------------------------------------
#define NCONV ((TOK * DIM) / 1024)     // 8192 conversion blocks

__global__ __launch_bounds__(256)
void prep_all(const float4* __restrict__ x4, uint2* __restrict__ of,
              const float* __restrict__ Wq, const float* __restrict__ Wk,
              const float* __restrict__ Wv, fp16* __restrict__ WT)
{
    const int b = blockIdx.x;
    if (b < NCONV) {
        const size_t i = (size_t)b * 256 + threadIdx.x;
        float4 v = x4[i];
        fp16 h[4] = {__float2half_rn(v.x), __float2half_rn(v.y),
                     __float2half_rn(v.z), __float2half_rn(v.w)};
        of[i] = *(uint2*)h;
        return;
    }
    // wtrans part
    __shared__ float t[32][33];
    const int widx = b - NCONV;         // 0..767
    const int w    = widx >> 8;         // 0,1,2 -> Wq,Wk,Wv
    const int r    = widx & 255;
    const int bx = (r & 15) * 32, by = (r >> 4) * 32;
    const float* W = (w == 0) ? Wq : (w == 1) ? Wk : Wv;
    fp16* T = WT + (size_t)w * DIM * DIM;
    const int tx = threadIdx.x & 31, ty = threadIdx.x >> 5;
    #pragma unroll
    for (int i = ty; i < 32; i += 8)
        t[i][tx] = W[(size_t)(by + i) * DIM + bx + tx];
    __syncthreads();
    #pragma unroll
    for (int i = ty; i < 32; i += 8)
        T[(size_t)(bx + i) * DIM + by + tx] = __float2half_rn(t[tx][i]);   // W^T
}

// ---------------------------------------------------------------------------
// Row softmax of P (fp32) -> fp16. One block per row (2048 cols).
// ---------------------------------------------------------------------------
__global__ __launch_bounds__(256)
void softmax_half(const float* __restrict__ P, fp16* __restrict__ Pf)
{
    const float* p = P + (size_t)blockIdx.x * SEQ;
    const int tid = threadIdx.x;
    __shared__ float red[8];

    float4 a = *(const float4*)&p[tid * 4];
    float4 b = *(const float4*)&p[1024 + tid * 4];
    float v[8] = {a.x, a.y, a.z, a.w, b.x, b.y, b.z, b.w};

    float m = v[0];
    #pragma unroll
    for (int i = 1; i < 8; i++) m = fmaxf(m, v[i]);
    #pragma unroll
    for (int o = 16; o > 0; o >>= 1) m = fmaxf(m, __shfl_xor_sync(~0u, m, o));
    if ((tid & 31) == 0) red[tid >> 5] = m;
    __syncthreads();
    m = red[0];
    #pragma unroll
    for (int i = 1; i < 8; i++) m = fmaxf(m, red[i]);
    __syncthreads();

    const float sc = 0.044194173824159216f;   // 1/sqrt(512)
    float s = 0.0f;
    #pragma unroll
    for (int i = 0; i < 8; i++) { v[i] = __expf((v[i] - m) * sc); s += v[i]; }
    #pragma unroll
    for (int o = 16; o > 0; o >>= 1) s += __shfl_xor_sync(~0u, s, o);
    if ((tid & 31) == 0) red[tid >> 5] = s;
    __syncthreads();
    s = 0.0f;
    #pragma unroll
    for (int i = 0; i < 8; i++) s += red[i];
    const float rinv = 1.0f / s;

    fp16 h[8];
    #pragma unroll
    for (int i = 0; i < 8; i++) h[i] = __float2half_rn(v[i] * rinv);
    const size_t base = (size_t)blockIdx.x * SEQ;
    *(uint2*)&Pf[base + tid * 4]        = *(uint2*)&h[0];
    *(uint2*)&Pf[base + 1024 + tid * 4] = *(uint2*)&h[4];
}

// ---------------------------------------------------------------------------
extern "C" void kernel_launch(void* const* d_in, const int* in_sizes, int n_in,
                              void* d_out, int out_size)
{
    const float* x  = (const float*)d_in[0];
    const float* Wq = (const float*)d_in[1];
    const float* Wk = (const float*)d_in[2];
    const float* Wv = (const float*)d_in[3];
    float* out = (float*)d_out;

    fp16 *Xf, *WT, *QK, *Vt, *Pf;
    float* P;
    cudaGetSymbolAddress((void**)&Xf, g_Xf);
    cudaGetSymbolAddress((void**)&WT, g_WT);
    cudaGetSymbolAddress((void**)&QK, g_QK);
    cudaGetSymbolAddress((void**)&Vt, g_Vt);
    cudaGetSymbolAddress((void**)&P, g_P);
    cudaGetSymbolAddress((void**)&Pf, g_Pf);

    const size_t QKs = (size_t)TOK * DIM;

    cudaFuncSetAttribute(gemm_mma<0>, cudaFuncAttributeMaxDynamicSharedMemorySize, SMEM_BYTES);
    cudaFuncSetAttribute(gemm_mma<1>, cudaFuncAttributeMaxDynamicSharedMemorySize, SMEM_BYTES);

    // launch 1: all conversions (x -> fp16, W -> W^T fp16)
    prep_all<<<NCONV + 768, 256>>>((const float4*)x, (uint2*)Xf, Wq, Wk, Wv, WT);

    // launch 2: Q,K projections (z=0 Wq, z=1 Wk). C fp16.
    gemm_mma<1><<<dim3(4, 128, 2), 256, SMEM_BYTES>>>(
        Xf, DIM, 0, WT, DIM, (size_t)DIM * DIM,
        nullptr, QK, DIM, QKs, DIM);
    // launch 3: V^T = Wv^T @ X^T. C fp16.
    gemm_mma<1><<<dim3(128, 4, 1), 256, SMEM_BYTES>>>(
        WT + 2 * DIM * DIM, DIM, 0, Xf, DIM, 0,
        nullptr, Vt, TOK, 0, DIM);

    // launch 4: scores P[b] = Q[b] @ K[b]^T. fp32 out.
    gemm_mma<0><<<dim3(16, 16, BATCH), 256, SMEM_BYTES>>>(
        QK, DIM, (size_t)SEQ * DIM, QK + QKs, DIM, (size_t)SEQ * DIM,
        P, nullptr, SEQ, (size_t)SEQ * SEQ, DIM);

    // launch 5: softmax rows -> fp16 probs
    softmax_half<<<BATCH * SEQ, 256>>>(P, Pf);

    // launch 6: out[b] = P[b] @ V[b] via B = V^T (ldb = TOK). fp32 out.
    gemm_mma<0><<<dim3(4, 16, BATCH), 256, SMEM_BYTES>>>(
        Pf, SEQ, (size_t)SEQ * SEQ, Vt, TOK, (size_t)SEQ,
        out, nullptr, DIM, (size_t)SEQ * DIM, SEQ);
}

// round 16
// speedup vs baseline: 1.0885x; 1.0414x over previous
#include <cuda_runtime.h>
#include <cuda_fp16.h>
#include <cstdint>

#define BATCH 8
#define SEQ   2048
#define DIM   512
#define TOK   (BATCH*SEQ)          // 16384

typedef __half fp16;

// ---------------------------------------------------------------------------
// Scratch (__device__ globals: allocation-guard safe)
// ---------------------------------------------------------------------------
__device__ fp16  g_Xf[(size_t)TOK * DIM];
__device__ fp16  g_WT[3][DIM * DIM];                       // W^T fp16
__device__ fp16  g_QK[2][(size_t)TOK * DIM];               // Q=0, K=1
__device__ fp16  g_Vt[(size_t)DIM * TOK];                  // V^T [512,16384]
__device__ fp16  g_Pf[(size_t)BATCH * SEQ * SEQ];          // scaled scores -> probs (in place)

// ---------------------------------------------------------------------------
// Baseline-PTX helpers (sm_80+: valid for compute_103 target)
// ---------------------------------------------------------------------------
__device__ __forceinline__ uint32_t s2u(const void* p) {
    uint32_t a;
    asm("{ .reg .u64 t; cvta.to.shared.u64 t, %1; cvt.u32.u64 %0, t; }" : "=r"(a) : "l"(p));
    return a;
}
__device__ __forceinline__ void cp16(uint32_t saddr, const fp16* g) {
    asm volatile("cp.async.cg.shared.global [%0], [%1], 16;"
                 :: "r"(saddr), "l"(__cvta_generic_to_global(g)) : "memory");
}
__device__ __forceinline__ void cp_commit() {
    asm volatile("cp.async.commit_group;" ::: "memory");
}
template <int N>
__device__ __forceinline__ void cp_wait() {
    asm volatile("cp.async.wait_group %0;" :: "n"(N) : "memory");
}
__device__ __forceinline__ void ldsm4(uint32_t* d, uint32_t a) {
    asm volatile("ldmatrix.sync.aligned.m8n8.x4.shared.b16 {%0,%1,%2,%3}, [%4];"
                 : "=r"(d[0]), "=r"(d[1]), "=r"(d[2]), "=r"(d[3]) : "r"(a));
}
__device__ __forceinline__ void mma16816(float* c, const uint32_t* a, const uint32_t* b) {
    asm volatile("mma.sync.aligned.m16n8k16.row.col.f32.f16.f16.f32 "
                 "{%0,%1,%2,%3}, {%4,%5,%6,%7}, {%8,%9}, {%0,%1,%2,%3};"
                 : "+f"(c[0]), "+f"(c[1]), "+f"(c[2]), "+f"(c[3])
                 : "r"(a[0]), "r"(a[1]), "r"(a[2]), "r"(a[3]), "r"(b[0]), "r"(b[1]));
}

// ---------------------------------------------------------------------------
// Single-pass fp16 GEMM: C[M,N] = cscale * (A·B^T)  (operands K-major fp16)
// CTA 128x128, BK=32, 256 threads, warp tile 32x64 (R12 — proven best).
// 4-stage cp.async pipeline, 2 CTAs/SM. EPI=0: fp32 C. EPI=1: fp16 C (scaled).
// grid = (N/128, M/128, batch). Mainloop byte-identical to R12.
// ---------------------------------------------------------------------------
#define STAGE_BYTES 16384          // 2 tiles x 8KB (A, B), 128 rows x 64B
#define NSTAGE      4
#define SMEM_BYTES  (NSTAGE * STAGE_BYTES)

template <int EPI>
__global__ __launch_bounds__(256, 2)
void gemm_mma(const fp16* __restrict__ A, int lda, size_t sA,
              const fp16* __restrict__ B, int ldb, size_t sB,
              float* __restrict__ C, fp16* __restrict__ Cf,
              int ldc, size_t sC, int Kd, float cscale)
{
    extern __shared__ __align__(1024) char smem[];
    const uint32_t sbase = s2u(smem);

    const int tid  = threadIdx.x;
    const int lane = tid & 31;
    const int wid  = tid >> 5;
    const int wm   = wid >> 1;        // 0..3 -> m offset wm*32
    const int wn   = wid & 1;         // 0..1 -> n offset wn*64

    A += (size_t)blockIdx.z * sA;
    B += (size_t)blockIdx.z * sB;
    if (C)  C  += (size_t)blockIdx.z * sC;
    if (Cf) Cf += (size_t)blockIdx.z * sC;
    const size_t bm = (size_t)blockIdx.y * 128;
    const size_t bn = (size_t)blockIdx.x * 128;

    const int nch = Kd >> 5;          // chunks of 32

    // gmem->smem: per tile 512 chunks of 16B; thread does rows cr0, cr0+64.
    // Swizzle: xch = ch ^ ((row>>1)&3).
    const int cr0 = tid >> 2;          // 0..63
    const int cch = tid & 3;
    const uint32_t s0 = (uint32_t)cr0 * 64 + (uint32_t)((cch ^ ((cr0 >> 1) & 3)) << 4);

    auto load_stage = [&](int stage, int c) {
        const uint32_t so = sbase + (uint32_t)stage * STAGE_BYTES;
        const size_t ka = (size_t)(c << 5) + cch * 8;
        const fp16* a_p = A + (bm + cr0) * (size_t)lda + ka;
        const fp16* b_p = B + (bn + cr0) * (size_t)ldb + ka;
        const size_t r64a = (size_t)64 * lda, r64b = (size_t)64 * ldb;
        cp16(so +         s0,         a_p);
        cp16(so +         s0 + 4096u, a_p + r64a);
        cp16(so + 8192u + s0,         b_p);
        cp16(so + 8192u + s0 + 4096u, b_p + r64b);
        cp_commit();
    };

    // ldmatrix per-lane pieces
    const int lg = lane >> 3, lr = lane & 7;
    const int a_row_off = (lg & 1) * 8 + lr;   // A-op (m-major)
    const int a_ch_off  = lg >> 1;
    const int b_row_off = (lg >> 1) * 8 + lr;  // B-op (n-major)
    const int b_ch_off  = lg & 1;

    uint32_t af[2][4], bf[4][4];

    auto frag_load = [&](uint32_t sb, int ks) {
        #pragma unroll
        for (int mt = 0; mt < 2; mt++) {
            const int row = wm * 32 + mt * 16 + a_row_off;
            const int ch  = 2 * ks + a_ch_off;
            const uint32_t off = (uint32_t)row * 64 + (uint32_t)(((ch ^ ((row >> 1) & 3)) & 3) << 4);
            ldsm4(af[mt], sb + off);
        }
        #pragma unroll
        for (int p = 0; p < 4; p++) {
            const int row = wn * 64 + p * 16 + b_row_off;
            const int ch  = 2 * ks + b_ch_off;
            const uint32_t off = (uint32_t)row * 64 + (uint32_t)(((ch ^ ((row >> 1) & 3)) & 3) << 4);
            ldsm4(bf[p], sb + 8192u + off);
        }
    };

    float acc[2][8][4];
    #pragma unroll
    for (int mt = 0; mt < 2; mt++)
        #pragma unroll
        for (int nt = 0; nt < 8; nt++)
            #pragma unroll
            for (int q = 0; q < 4; q++) acc[mt][nt][q] = 0.0f;

    auto compute = [&]() {
        #pragma unroll
        for (int mt = 0; mt < 2; mt++)
            #pragma unroll
            for (int p = 0; p < 4; p++) {
                mma16816(acc[mt][2 * p],     af[mt], &bf[p][0]);
                mma16816(acc[mt][2 * p + 1], af[mt], &bf[p][2]);
            }
    };

    // 4-stage pipeline prologue: stages 0,1,2 in flight
    load_stage(0, 0);
    load_stage(1, 1);
    if (nch > 2) load_stage(2, 2);

    int slot = 0;
    for (int c = 0; c < nch; c++) {
        if (c + 2 < nch)      cp_wait<2>();
        else if (c + 1 < nch) cp_wait<1>();
        else                  cp_wait<0>();
        __syncthreads();

        const uint32_t sb = sbase + (uint32_t)slot * STAGE_BYTES;
        frag_load(sb, 0);
        compute();
        frag_load(sb, 1);
        compute();

        if (c + 3 < nch) {
            int nslot = slot + 3; if (nslot >= NSTAGE) nslot -= NSTAGE;
            load_stage(nslot, c + 3);
        }
        if (++slot == NSTAGE) slot = 0;
    }

    // Epilogue: m16n8k16 acc: c0,c1 -> (r, c),(r, c+1); c2,c3 -> (r+8, ..)
    const int er = lane >> 2, ec = (lane & 3) * 2;
    #pragma unroll
    for (int mt = 0; mt < 2; mt++) {
        const size_t row0 = bm + wm * 32 + mt * 16 + er;
        #pragma unroll
        for (int nt = 0; nt < 8; nt++) {
            const size_t col = bn + wn * 64 + nt * 8 + ec;
            if (EPI == 0) {
                float2 v0 = make_float2(acc[mt][nt][0], acc[mt][nt][1]);
                float2 v1 = make_float2(acc[mt][nt][2], acc[mt][nt][3]);
                *(float2*)&C[row0 * ldc + col]       = v0;
                *(float2*)&C[(row0 + 8) * ldc + col] = v1;
            } else {
                *(__half2*)&Cf[row0 * ldc + col] =
                    __halves2half2(__float2half_rn(acc[mt][nt][0] * cscale),
                                   __float2half_rn(acc[mt][nt][1] * cscale));
                *(__half2*)&Cf[(row0 + 8) * ldc + col] =
                    __halves2half2(__float2half_rn(acc[mt][nt][2] * cscale),
                                   __float2half_rn(acc[mt][nt][3] * cscale));
            }
        }
    }
}

// ---------------------------------------------------------------------------
// Merged prep kernel: one launch does
//   blocks [0, NCONV)          : x fp32 -> Xf fp16 (float4 per thread)
//   blocks [NCONV, NCONV+768)  : W{q,k,v} -> W^T fp16 (32x32 transpose)
// ---------------------------------------------------------------------------
#define NCONV ((TOK * DIM) / 1024)     // 8192 conversion blocks

__global__ __launch_bounds__(256)
void prep_all(const float4* __restrict__ x4, uint2* __restrict__ of,
              const float* __restrict__ Wq, const float* __restrict__ Wk,
              const float* __restrict__ Wv, fp16* __restrict__ WT)
{
    const int b = blockIdx.x;
    if (b < NCONV) {
        const size_t i = (size_t)b * 256 + threadIdx.x;
        float4 v = x4[i];
        fp16 h[4] = {__float2half_rn(v.x), __float2half_rn(v.y),
                     __float2half_rn(v.z), __float2half_rn(v.w)};
        of[i] = *(uint2*)h;
        return;
    }
    // wtrans part
    __shared__ float t[32][33];
    const int widx = b - NCONV;         // 0..767
    const int w    = widx >> 8;         // 0,1,2 -> Wq,Wk,Wv
    const int r    = widx & 255;
    const int bx = (r & 15) * 32, by = (r >> 4) * 32;
    const float* W = (w == 0) ? Wq : (w == 1) ? Wk : Wv;
    fp16* T = WT + (size_t)w * DIM * DIM;
    const int tx = threadIdx.x & 31, ty = threadIdx.x >> 5;
    #pragma unroll
    for (int i = ty; i < 32; i += 8)
        t[i][tx] = W[(size_t)(by + i) * DIM + bx + tx];
    __syncthreads();
    #pragma unroll
    for (int i = ty; i < 32; i += 8)
        T[(size_t)(bx + i) * DIM + by + tx] = __float2half_rn(t[tx][i]);   // W^T
}

// ---------------------------------------------------------------------------
// Row softmax IN PLACE on fp16 pre-scaled scores (scale 1/sqrt(512) already
// applied in the QK^T epilogue). One block (256 threads) per row of 2048.
// Each thread reads its 8 values before any writes -> in-place safe.
// ---------------------------------------------------------------------------
__global__ __launch_bounds__(256)
void softmax_half(fp16* __restrict__ Pf)
{
    const size_t base = (size_t)blockIdx.x * SEQ;
    const int tid = threadIdx.x;
    __shared__ float red[8];

    uint2 r0 = *(uint2*)&Pf[base + tid * 4];
    uint2 r1 = *(uint2*)&Pf[base + 1024 + tid * 4];
    float v[8];
    {
        const fp16* p0 = (const fp16*)&r0;
        const fp16* p1 = (const fp16*)&r1;
        #pragma unroll
        for (int i = 0; i < 4; i++) {
            v[i]     = __half2float(p0[i]);
            v[4 + i] = __half2float(p1[i]);
        }
    }

    float m = v[0];
    #pragma unroll
    for (int i = 1; i < 8; i++) m = fmaxf(m, v[i]);
    #pragma unroll
    for (int o = 16; o > 0; o >>= 1) m = fmaxf(m, __shfl_xor_sync(~0u, m, o));
    if ((tid & 31) == 0) red[tid >> 5] = m;
    __syncthreads();
    m = red[0];
    #pragma unroll
    for (int i = 1; i < 8; i++) m = fmaxf(m, red[i]);
    __syncthreads();

    float s = 0.0f;
    #pragma unroll
    for (int i = 0; i < 8; i++) { v[i] = __expf(v[i] - m); s += v[i]; }
    #pragma unroll
    for (int o = 16; o > 0; o >>= 1) s += __shfl_xor_sync(~0u, s, o);
    if ((tid & 31) == 0) red[tid >> 5] = s;
    __syncthreads();
    s = 0.0f;
    #pragma unroll
    for (int i = 0; i < 8; i++) s += red[i];
    const float rinv = 1.0f / s;

    fp16 h[8];
    #pragma unroll
    for (int i = 0; i < 8; i++) h[i] = __float2half_rn(v[i] * rinv);
    *(uint2*)&Pf[base + tid * 4]        = *(uint2*)&h[0];
    *(uint2*)&Pf[base + 1024 + tid * 4] = *(uint2*)&h[4];
}

// ---------------------------------------------------------------------------
extern "C" void kernel_launch(void* const* d_in, const int* in_sizes, int n_in,
                              void* d_out, int out_size)
{
    const float* x  = (const float*)d_in[0];
    const float* Wq = (const float*)d_in[1];
    const float* Wk = (const float*)d_in[2];
    const float* Wv = (const float*)d_in[3];
    float* out = (float*)d_out;

    fp16 *Xf, *WT, *QK, *Vt, *Pf;
    cudaGetSymbolAddress((void**)&Xf, g_Xf);
    cudaGetSymbolAddress((void**)&WT, g_WT);
    cudaGetSymbolAddress((void**)&QK, g_QK);
    cudaGetSymbolAddress((void**)&Vt, g_Vt);
    cudaGetSymbolAddress((void**)&Pf, g_Pf);

    const size_t QKs = (size_t)TOK * DIM;

    cudaFuncSetAttribute(gemm_mma<0>, cudaFuncAttributeMaxDynamicSharedMemorySize, SMEM_BYTES);
    cudaFuncSetAttribute(gemm_mma<1>, cudaFuncAttributeMaxDynamicSharedMemorySize, SMEM_BYTES);

    // launch 1: all conversions (x -> fp16, W -> W^T fp16)
    prep_all<<<NCONV + 768, 256>>>((const float4*)x, (uint2*)Xf, Wq, Wk, Wv, WT);

    // launch 2: Q,K projections (z=0 Wq, z=1 Wk). C fp16, scale 1.
    gemm_mma<1><<<dim3(4, 128, 2), 256, SMEM_BYTES>>>(
        Xf, DIM, 0, WT, DIM, (size_t)DIM * DIM,
        nullptr, QK, DIM, QKs, DIM, 1.0f);
    // launch 3: V^T = Wv^T @ X^T. C fp16, scale 1.
    gemm_mma<1><<<dim3(128, 4, 1), 256, SMEM_BYTES>>>(
        WT + 2 * DIM * DIM, DIM, 0, Xf, DIM, 0,
        nullptr, Vt, TOK, 0, DIM, 1.0f);

    // launch 4: scaled scores S[b] = (Q[b] @ K[b]^T)/sqrt(512) -> fp16 (64 MB)
    gemm_mma<1><<<dim3(16, 16, BATCH), 256, SMEM_BYTES>>>(
        QK, DIM, (size_t)SEQ * DIM, QK + QKs, DIM, (size_t)SEQ * DIM,
        nullptr, Pf, SEQ, (size_t)SEQ * SEQ, DIM, 0.044194173824159216f);

    // launch 5: softmax in place on fp16 scaled scores
    softmax_half<<<BATCH * SEQ, 256>>>(Pf);

    // launch 6: out[b] = P[b] @ V[b] via B = V^T (ldb = TOK). fp32 out.
    gemm_mma<0><<<dim3(4, 16, BATCH), 256, SMEM_BYTES>>>(
        Pf, SEQ, (size_t)SEQ * SEQ, Vt, TOK, (size_t)SEQ,
        out, nullptr, DIM, (size_t)SEQ * DIM, SEQ, 1.0f);
}

// round 17
// speedup vs baseline: 1.1181x; 1.0272x over previous
#include <cuda_runtime.h>
#include <cuda_fp16.h>
#include <cstdint>

#define BATCH 8
#define SEQ   2048
#define DIM   512
#define TOK   (BATCH*SEQ)          // 16384

typedef __half fp16;

// ---------------------------------------------------------------------------
// Scratch (__device__ globals: allocation-guard safe)
// ---------------------------------------------------------------------------
__device__ fp16  g_Xf[(size_t)TOK * DIM];
__device__ fp16  g_WT[3][DIM * DIM];                       // W^T fp16
__device__ fp16  g_QK[2][(size_t)TOK * DIM];               // Q=0, K=1
__device__ fp16  g_Vt[(size_t)DIM * TOK];                  // V^T [512,16384]
__device__ fp16  g_Pf[(size_t)BATCH * SEQ * SEQ];          // exp(scaled scores), fp16
__device__ float g_RS[32 * (size_t)TOK];                   // partial row sums [slot][row]
__device__ float g_rinv[TOK];                              // 1 / row sum

// ---------------------------------------------------------------------------
// Baseline-PTX helpers (sm_80+: valid for compute_103 target)
// ---------------------------------------------------------------------------
__device__ __forceinline__ uint32_t s2u(const void* p) {
    uint32_t a;
    asm("{ .reg .u64 t; cvta.to.shared.u64 t, %1; cvt.u32.u64 %0, t; }" : "=r"(a) : "l"(p));
    return a;
}
__device__ __forceinline__ void cp16(uint32_t saddr, const fp16* g) {
    asm volatile("cp.async.cg.shared.global [%0], [%1], 16;"
                 :: "r"(saddr), "l"(__cvta_generic_to_global(g)) : "memory");
}
__device__ __forceinline__ void cp_commit() {
    asm volatile("cp.async.commit_group;" ::: "memory");
}
template <int N>
__device__ __forceinline__ void cp_wait() {
    asm volatile("cp.async.wait_group %0;" :: "n"(N) : "memory");
}
__device__ __forceinline__ void ldsm4(uint32_t* d, uint32_t a) {
    asm volatile("ldmatrix.sync.aligned.m8n8.x4.shared.b16 {%0,%1,%2,%3}, [%4];"
                 : "=r"(d[0]), "=r"(d[1]), "=r"(d[2]), "=r"(d[3]) : "r"(a));
}
__device__ __forceinline__ void mma16816(float* c, const uint32_t* a, const uint32_t* b) {
    asm volatile("mma.sync.aligned.m16n8k16.row.col.f32.f16.f16.f32 "
                 "{%0,%1,%2,%3}, {%4,%5,%6,%7}, {%8,%9}, {%0,%1,%2,%3};"
                 : "+f"(c[0]), "+f"(c[1]), "+f"(c[2]), "+f"(c[3])
                 : "r"(a[0]), "r"(a[1]), "r"(a[2]), "r"(a[3]), "r"(b[0]), "r"(b[1]));
}

// ---------------------------------------------------------------------------
// Single-pass fp16 GEMM, R12-proven mainloop (CTA 128x128, BK=32, warp tile
// 32x64, 4-stage cp.async, 2 CTAs/SM). Epilogue variants:
//   EPI=1: Cf = fp16(cscale * acc)
//   EPI=2: Cf = fp16(exp(cscale * acc)); deterministic partial row sums -> RS
//   EPI=3: C  = fp32(acc * rinv[row])   (PV normalization)
// grid = (N/128, M/128, batch)
// ---------------------------------------------------------------------------
#define STAGE_BYTES 16384          // 2 tiles x 8KB (A, B), 128 rows x 64B
#define NSTAGE      4
#define SMEM_BYTES  (NSTAGE * STAGE_BYTES)

template <int EPI>
__global__ __launch_bounds__(256, 2)
void gemm_mma(const fp16* __restrict__ A, int lda, size_t sA,
              const fp16* __restrict__ B, int ldb, size_t sB,
              float* __restrict__ C, fp16* __restrict__ Cf,
              int ldc, size_t sC, int Kd, float cscale,
              float* __restrict__ RS, const float* __restrict__ rinv)
{
    extern __shared__ __align__(1024) char smem[];
    const uint32_t sbase = s2u(smem);

    const int tid  = threadIdx.x;
    const int lane = tid & 31;
    const int wid  = tid >> 5;
    const int wm   = wid >> 1;        // 0..3 -> m offset wm*32
    const int wn   = wid & 1;         // 0..1 -> n offset wn*64

    A += (size_t)blockIdx.z * sA;
    B += (size_t)blockIdx.z * sB;
    if (C)  C  += (size_t)blockIdx.z * sC;
    if (Cf) Cf += (size_t)blockIdx.z * sC;
    const size_t bm = (size_t)blockIdx.y * 128;
    const size_t bn = (size_t)blockIdx.x * 128;

    const int nch = Kd >> 5;          // chunks of 32

    // gmem->smem: per tile 512 chunks of 16B; thread does rows cr0, cr0+64.
    // Swizzle: xch = ch ^ ((row>>1)&3).
    const int cr0 = tid >> 2;          // 0..63
    const int cch = tid & 3;
    const uint32_t s0 = (uint32_t)cr0 * 64 + (uint32_t)((cch ^ ((cr0 >> 1) & 3)) << 4);

    auto load_stage = [&](int stage, int c) {
        const uint32_t so = sbase + (uint32_t)stage * STAGE_BYTES;
        const size_t ka = (size_t)(c << 5) + cch * 8;
        const fp16* a_p = A + (bm + cr0) * (size_t)lda + ka;
        const fp16* b_p = B + (bn + cr0) * (size_t)ldb + ka;
        const size_t r64a = (size_t)64 * lda, r64b = (size_t)64 * ldb;
        cp16(so +         s0,         a_p);
        cp16(so +         s0 + 4096u, a_p + r64a);
        cp16(so + 8192u + s0,         b_p);
        cp16(so + 8192u + s0 + 4096u, b_p + r64b);
        cp_commit();
    };

    // ldmatrix per-lane pieces
    const int lg = lane >> 3, lr = lane & 7;
    const int a_row_off = (lg & 1) * 8 + lr;   // A-op (m-major)
    const int a_ch_off  = lg >> 1;
    const int b_row_off = (lg >> 1) * 8 + lr;  // B-op (n-major)
    const int b_ch_off  = lg & 1;

    uint32_t af[2][4], bf[4][4];

    auto frag_load = [&](uint32_t sb, int ks) {
        #pragma unroll
        for (int mt = 0; mt < 2; mt++) {
            const int row = wm * 32 + mt * 16 + a_row_off;
            const int ch  = 2 * ks + a_ch_off;
            const uint32_t off = (uint32_t)row * 64 + (uint32_t)(((ch ^ ((row >> 1) & 3)) & 3) << 4);
            ldsm4(af[mt], sb + off);
        }
        #pragma unroll
        for (int p = 0; p < 4; p++) {
            const int row = wn * 64 + p * 16 + b_row_off;
            const int ch  = 2 * ks + b_ch_off;
            const uint32_t off = (uint32_t)row * 64 + (uint32_t)(((ch ^ ((row >> 1) & 3)) & 3) << 4);
            ldsm4(bf[p], sb + 8192u + off);
        }
    };

    float acc[2][8][4];
    #pragma unroll
    for (int mt = 0; mt < 2; mt++)
        #pragma unroll
        for (int nt = 0; nt < 8; nt++)
            #pragma unroll
            for (int q = 0; q < 4; q++) acc[mt][nt][q] = 0.0f;

    auto compute = [&]() {
        #pragma unroll
        for (int mt = 0; mt < 2; mt++)
            #pragma unroll
            for (int p = 0; p < 4; p++) {
                mma16816(acc[mt][2 * p],     af[mt], &bf[p][0]);
                mma16816(acc[mt][2 * p + 1], af[mt], &bf[p][2]);
            }
    };

    // 4-stage pipeline prologue: stages 0,1,2 in flight
    load_stage(0, 0);
    load_stage(1, 1);
    if (nch > 2) load_stage(2, 2);

    int slot = 0;
    for (int c = 0; c < nch; c++) {
        if (c + 2 < nch)      cp_wait<2>();
        else if (c + 1 < nch) cp_wait<1>();
        else                  cp_wait<0>();
        __syncthreads();

        const uint32_t sb = sbase + (uint32_t)slot * STAGE_BYTES;
        frag_load(sb, 0);
        compute();
        frag_load(sb, 1);
        compute();

        if (c + 3 < nch) {
            int nslot = slot + 3; if (nslot >= NSTAGE) nslot -= NSTAGE;
            load_stage(nslot, c + 3);
        }
        if (++slot == NSTAGE) slot = 0;
    }

    // Epilogue: m16n8k16 acc: c0,c1 -> (r, c),(r, c+1); c2,c3 -> (r+8, ..)
    const int er = lane >> 2, ec = (lane & 3) * 2;
    float rs_lo[2] = {0.0f, 0.0f}, rs_hi[2] = {0.0f, 0.0f};

    #pragma unroll
    for (int mt = 0; mt < 2; mt++) {
        const size_t row0 = bm + wm * 32 + mt * 16 + er;
        float ri_a = 1.0f, ri_b = 1.0f;
        if (EPI == 3) {
            const size_t gr = (size_t)blockIdx.z * SEQ + row0;
            ri_a = __ldg(&rinv[gr]);
            ri_b = __ldg(&rinv[gr + 8]);
        }
        #pragma unroll
        for (int nt = 0; nt < 8; nt++) {
            const size_t col = bn + wn * 64 + nt * 8 + ec;
            if (EPI == 3) {
                float2 v0 = make_float2(acc[mt][nt][0] * ri_a, acc[mt][nt][1] * ri_a);
                float2 v1 = make_float2(acc[mt][nt][2] * ri_b, acc[mt][nt][3] * ri_b);
                *(float2*)&C[row0 * ldc + col]       = v0;
                *(float2*)&C[(row0 + 8) * ldc + col] = v1;
            } else if (EPI == 2) {
                float e0 = __expf(acc[mt][nt][0] * cscale);
                float e1 = __expf(acc[mt][nt][1] * cscale);
                float e2 = __expf(acc[mt][nt][2] * cscale);
                float e3 = __expf(acc[mt][nt][3] * cscale);
                *(__half2*)&Cf[row0 * ldc + col] =
                    __halves2half2(__float2half_rn(e0), __float2half_rn(e1));
                *(__half2*)&Cf[(row0 + 8) * ldc + col] =
                    __halves2half2(__float2half_rn(e2), __float2half_rn(e3));
                rs_lo[mt] += e0 + e1;
                rs_hi[mt] += e2 + e3;
            } else {  // EPI == 1
                *(__half2*)&Cf[row0 * ldc + col] =
                    __halves2half2(__float2half_rn(acc[mt][nt][0] * cscale),
                                   __float2half_rn(acc[mt][nt][1] * cscale));
                *(__half2*)&Cf[(row0 + 8) * ldc + col] =
                    __halves2half2(__float2half_rn(acc[mt][nt][2] * cscale),
                                   __float2half_rn(acc[mt][nt][3] * cscale));
            }
        }
    }

    if (EPI == 2) {
        // reduce partial sums over the 4 lanes sharing each row (lane&3 varies)
        #pragma unroll
        for (int mt = 0; mt < 2; mt++) {
            #pragma unroll
            for (int o = 1; o < 4; o <<= 1) {
                rs_lo[mt] += __shfl_xor_sync(~0u, rs_lo[mt], o);
                rs_hi[mt] += __shfl_xor_sync(~0u, rs_hi[mt], o);
            }
        }
        if ((lane & 3) == 0) {
            const int slot32 = (int)blockIdx.x * 2 + wn;   // 0..31, unique per (N-tile, wn)
            #pragma unroll
            for (int mt = 0; mt < 2; mt++) {
                const size_t gr = (size_t)blockIdx.z * SEQ + bm + wm * 32 + mt * 16 + er;
                RS[(size_t)slot32 * TOK + gr]     = rs_lo[mt];
                RS[(size_t)slot32 * TOK + gr + 8] = rs_hi[mt];
            }
        }
    }
}

// ---------------------------------------------------------------------------
// Merged prep kernel: one launch does
//   blocks [0, NCONV)          : x fp32 -> Xf fp16 (float4 per thread)
//   blocks [NCONV, NCONV+768)  : W{q,k,v} -> W^T fp16 (32x32 transpose)
// ---------------------------------------------------------------------------
#define NCONV ((TOK * DIM) / 1024)     // 8192 conversion blocks

__global__ __launch_bounds__(256)
void prep_all(const float4* __restrict__ x4, uint2* __restrict__ of,
              const float* __restrict__ Wq, const float* __restrict__ Wk,
              const float* __restrict__ Wv, fp16* __restrict__ WT)
{
    const int b = blockIdx.x;
    if (b < NCONV) {
        const size_t i = (size_t)b * 256 + threadIdx.x;
        float4 v = x4[i];
        fp16 h[4] = {__float2half_rn(v.x), __float2half_rn(v.y),
                     __float2half_rn(v.z), __float2half_rn(v.w)};
        of[i] = *(uint2*)h;
        return;
    }
    // wtrans part
    __shared__ float t[32][33];
    const int widx = b - NCONV;         // 0..767
    const int w    = widx >> 8;         // 0,1,2 -> Wq,Wk,Wv
    const int r    = widx & 255;
    const int bx = (r & 15) * 32, by = (r >> 4) * 32;
    const float* W = (w == 0) ? Wq : (w == 1) ? Wk : Wv;
    fp16* T = WT + (size_t)w * DIM * DIM;
    const int tx = threadIdx.x & 31, ty = threadIdx.x >> 5;
    #pragma unroll
    for (int i = ty; i < 32; i += 8)
        t[i][tx] = W[(size_t)(by + i) * DIM + bx + tx];
    __syncthreads();
    #pragma unroll
    for (int i = ty; i < 32; i += 8)
        T[(size_t)(bx + i) * DIM + by + tx] = __float2half_rn(t[tx][i]);   // W^T
}

// ---------------------------------------------------------------------------
// rowsum finalize: rinv[r] = 1 / sum_{s<32} RS[s][r].  TOK threads total.
// ---------------------------------------------------------------------------
__global__ __launch_bounds__(256)
void rowsum_inv(const float* __restrict__ RS, float* __restrict__ rinv)
{
    const int r = blockIdx.x * 256 + threadIdx.x;
    float s = 0.0f;
    #pragma unroll
    for (int k = 0; k < 32; k++) s += RS[(size_t)k * TOK + r];
    rinv[r] = 1.0f / s;
}

// ---------------------------------------------------------------------------
extern "C" void kernel_launch(void* const* d_in, const int* in_sizes, int n_in,
                              void* d_out, int out_size)
{
    const float* x  = (const float*)d_in[0];
    const float* Wq = (const float*)d_in[1];
    const float* Wk = (const float*)d_in[2];
    const float* Wv = (const float*)d_in[3];
    float* out = (float*)d_out;

    fp16 *Xf, *WT, *QK, *Vt, *Pf;
    float *RS, *rinv;
    cudaGetSymbolAddress((void**)&Xf, g_Xf);
    cudaGetSymbolAddress((void**)&WT, g_WT);
    cudaGetSymbolAddress((void**)&QK, g_QK);
    cudaGetSymbolAddress((void**)&Vt, g_Vt);
    cudaGetSymbolAddress((void**)&Pf, g_Pf);
    cudaGetSymbolAddress((void**)&RS, g_RS);
    cudaGetSymbolAddress((void**)&rinv, g_rinv);

    const size_t QKs = (size_t)TOK * DIM;

    cudaFuncSetAttribute(gemm_mma<1>, cudaFuncAttributeMaxDynamicSharedMemorySize, SMEM_BYTES);
    cudaFuncSetAttribute(gemm_mma<2>, cudaFuncAttributeMaxDynamicSharedMemorySize, SMEM_BYTES);
    cudaFuncSetAttribute(gemm_mma<3>, cudaFuncAttributeMaxDynamicSharedMemorySize, SMEM_BYTES);

    // launch 1: all conversions (x -> fp16, W -> W^T fp16)
    prep_all<<<NCONV + 768, 256>>>((const float4*)x, (uint2*)Xf, Wq, Wk, Wv, WT);

    // launch 2: Q,K projections (z=0 Wq, z=1 Wk). C fp16, scale 1.
    gemm_mma<1><<<dim3(4, 128, 2), 256, SMEM_BYTES>>>(
        Xf, DIM, 0, WT, DIM, (size_t)DIM * DIM,
        nullptr, QK, DIM, QKs, DIM, 1.0f, nullptr, nullptr);
    // launch 3: V^T = Wv^T @ X^T. C fp16, scale 1.
    gemm_mma<1><<<dim3(128, 4, 1), 256, SMEM_BYTES>>>(
        WT + 2 * DIM * DIM, DIM, 0, Xf, DIM, 0,
        nullptr, Vt, TOK, 0, DIM, 1.0f, nullptr, nullptr);

    // launch 4: E[b] = exp((Q[b] @ K[b]^T)/sqrt(512)) -> fp16, + partial row sums
    gemm_mma<2><<<dim3(16, 16, BATCH), 256, SMEM_BYTES>>>(
        QK, DIM, (size_t)SEQ * DIM, QK + QKs, DIM, (size_t)SEQ * DIM,
        nullptr, Pf, SEQ, (size_t)SEQ * SEQ, DIM, 0.044194173824159216f, RS, nullptr);

    // launch 5: rinv[r] = 1 / row sum (tiny)
    rowsum_inv<<<TOK / 256, 256>>>(RS, rinv);

    // launch 6: out[b] = (E[b] @ V[b]) * rinv  via B = V^T (ldb = TOK). fp32 out.
    gemm_mma<3><<<dim3(4, 16, BATCH), 256, SMEM_BYTES>>>(
        Pf, SEQ, (size_t)SEQ * SEQ, Vt, TOK, (size_t)SEQ,
        out, nullptr, DIM, (size_t)SEQ * DIM, SEQ, 1.0f, nullptr, rinv);
}